// round 1
// baseline (speedup 1.0000x reference)
#include <cuda_runtime.h>

// ---------------- problem dims ----------------
#define MDIM 16384   // B*S
#define NDIM 1024    // DM
#define KDIM 1024    // DM
#define HEADS 16
#define DEPTH 64

// ---------------- GEMM tiling ----------------
#define BM 128
#define BN 128
#define BK 32
#define APAD 36      // A smem row stride (floats): conflict-free frag reads, 16B aligned
#define BPAD 136     // B smem row stride (floats): conflict-free frag reads, 16B aligned
#define ASZ (BM * APAD)   // 4608 floats per stage
#define BSZ (BK * BPAD)   // 4352 floats per stage
#define GEMM_SMEM ((2 * (ASZ + BSZ)) * 4)   // 71680 bytes

// ---------------- scratch (no allocs allowed) ----------------
__device__ float g_q[(size_t)MDIM * NDIM];
__device__ float g_k[(size_t)MDIM * NDIM];
__device__ float g_v[(size_t)MDIM * NDIM];
__device__ float g_attn[(size_t)MDIM * NDIM];

// ---------------- helpers ----------------
__device__ __forceinline__ unsigned f2tf(float x) {
    unsigned r;
    asm("cvt.rna.tf32.f32 %0, %1;" : "=r"(r) : "f"(x));
    return r;
}

__device__ __forceinline__ void cp_async16(void* smem_ptr, const void* gmem_ptr) {
    unsigned s = (unsigned)__cvta_generic_to_shared(smem_ptr);
    asm volatile("cp.async.cg.shared.global [%0], [%1], 16;\n" :: "r"(s), "l"(gmem_ptr));
}

__device__ __forceinline__ void mma_tf32(float c[4], const unsigned a[4], const unsigned b[2]) {
    asm volatile(
        "mma.sync.aligned.m16n8k8.row.col.f32.tf32.tf32.f32 "
        "{%0,%1,%2,%3}, {%4,%5,%6,%7}, {%8,%9}, {%0,%1,%2,%3};\n"
        : "+f"(c[0]), "+f"(c[1]), "+f"(c[2]), "+f"(c[3])
        : "r"(a[0]), "r"(a[1]), "r"(a[2]), "r"(a[3]), "r"(b[0]), "r"(b[1]));
}

// ---------------- GEMM: C[M,N] = A[M,K] @ B[K,N] + bias[N]  (tf32 mma) ----------------
__global__ void __launch_bounds__(256, 2) gemm_tf32(
    const float* __restrict__ A, const float* __restrict__ B,
    const float* __restrict__ bias, float* __restrict__ C, float* __restrict__ C2)
{
    extern __shared__ float sm[];
    float* As = sm;            // 2 stages of ASZ
    float* Bs = sm + 2 * ASZ;  // 2 stages of BSZ

    const int m0 = blockIdx.y * BM;
    const int n0 = blockIdx.x * BN;
    const int t = threadIdx.x;
    const int warp = t >> 5, lane = t & 31;
    const int wm = (warp >> 2) * 64;   // 2 warps in M
    const int wn = (warp & 3) * 32;    // 4 warps in N
    const int grp = lane >> 2, tig = lane & 3;

    float acc[4][4][4];
#pragma unroll
    for (int mi = 0; mi < 4; mi++)
#pragma unroll
        for (int ni = 0; ni < 4; ni++)
#pragma unroll
            for (int r = 0; r < 4; r++) acc[mi][ni][r] = 0.f;

    auto loadTile = [&](int s, int kt) {
        // A tile: 128 rows x 32 cols (8 float4/row), 1024 float4s / 256 thr = 4 each
#pragma unroll
        for (int i = 0; i < 4; i++) {
            int idx = t + i * 256;
            int row = idx >> 3, cv = idx & 7;
            cp_async16(&As[s * ASZ + row * APAD + cv * 4],
                       &A[(size_t)(m0 + row) * KDIM + kt * BK + cv * 4]);
        }
        // B tile: 32 rows x 128 cols (32 float4/row)
#pragma unroll
        for (int i = 0; i < 4; i++) {
            int idx = t + i * 256;
            int row = idx >> 5, cv = idx & 31;
            cp_async16(&Bs[s * BSZ + row * BPAD + cv * 4],
                       &B[(size_t)(kt * BK + row) * NDIM + n0 + cv * 4]);
        }
        asm volatile("cp.async.commit_group;\n");
    };

    auto compute = [&](int s) {
        const float* as = &As[s * ASZ];
        const float* bs = &Bs[s * BSZ];
#pragma unroll
        for (int ks = 0; ks < 4; ks++) {
            const int kb = ks * 8;
            unsigned af[4][4];
#pragma unroll
            for (int mi = 0; mi < 4; mi++) {
                const float* ap = as + (wm + mi * 16 + grp) * APAD + kb + tig;
                af[mi][0] = f2tf(ap[0]);
                af[mi][1] = f2tf(ap[8 * APAD]);
                af[mi][2] = f2tf(ap[4]);
                af[mi][3] = f2tf(ap[8 * APAD + 4]);
            }
            unsigned bf[4][2];
#pragma unroll
            for (int ni = 0; ni < 4; ni++) {
                const float* bp = bs + (kb + tig) * BPAD + wn + ni * 8 + grp;
                bf[ni][0] = f2tf(bp[0]);
                bf[ni][1] = f2tf(bp[4 * BPAD]);
            }
#pragma unroll
            for (int mi = 0; mi < 4; mi++)
#pragma unroll
                for (int ni = 0; ni < 4; ni++)
                    mma_tf32(acc[mi][ni], af[mi], bf[ni]);
        }
    };

    loadTile(0, 0);
    const int nt = KDIM / BK;  // 32
    for (int kt = 0; kt < nt; kt++) {
        if (kt + 1 < nt) {
            loadTile((kt + 1) & 1, kt + 1);
            asm volatile("cp.async.wait_group 1;\n");
        } else {
            asm volatile("cp.async.wait_group 0;\n");
        }
        __syncthreads();
        compute(kt & 1);
        __syncthreads();
    }

    // epilogue: +bias, fp32 stores (optionally duplicated)
#pragma unroll
    for (int mi = 0; mi < 4; mi++) {
        const int r0 = m0 + wm + mi * 16 + grp;
#pragma unroll
        for (int ni = 0; ni < 4; ni++) {
            const int col = n0 + wn + ni * 8 + tig * 2;
            float2 bv = *(const float2*)&bias[col];
            float2 lo = make_float2(acc[mi][ni][0] + bv.x, acc[mi][ni][1] + bv.y);
            float2 hi = make_float2(acc[mi][ni][2] + bv.x, acc[mi][ni][3] + bv.y);
            *(float2*)&C[(size_t)r0 * NDIM + col] = lo;
            *(float2*)&C[(size_t)(r0 + 8) * NDIM + col] = hi;
            if (C2) {
                *(float2*)&C2[(size_t)r0 * NDIM + col] = lo;
                *(float2*)&C2[(size_t)(r0 + 8) * NDIM + col] = hi;
            }
        }
    }
}

// ---------------- per-token head-axis attention ----------------
// scores[h,g] = q[h,:]·k[g,:]/8 + mask*(-1e9); softmax over g; out[h,:] = w·v
#define AT_WARPS 2
#define ROWP 68                 // padded row stride for q/k/v in smem
#define WSTRIDE (3 * 16 * ROWP + 16 * 17)   // 3*1088 + 272 = 3536 floats/warp

__global__ void attn_kernel(const float* __restrict__ qg, const float* __restrict__ kg,
                            const float* __restrict__ vg, const float* __restrict__ mg,
                            float* __restrict__ outg)
{
    __shared__ float sm[AT_WARPS * WSTRIDE];
    const int warp = threadIdx.x >> 5, lane = threadIdx.x & 31;
    const int tok = blockIdx.x * AT_WARPS + warp;
    float* sq = sm + warp * WSTRIDE;
    float* sk = sq + 16 * ROWP;
    float* sv = sk + 16 * ROWP;
    float* sw = sv + 16 * ROWP;
    const size_t base = (size_t)tok * 1024;

    // stage q,k,v rows (16x64 each) into padded smem
#pragma unroll
    for (int i = 0; i < 8; i++) {
        int idx = lane + i * 32;                 // 0..255 float4s
        int row = idx >> 4, col = (idx & 15) * 4;
        *(float4*)&sq[row * ROWP + col] = *(const float4*)&qg[base + row * 64 + col];
        *(float4*)&sk[row * ROWP + col] = *(const float4*)&kg[base + row * 64 + col];
        *(float4*)&sv[row * ROWP + col] = *(const float4*)&vg[base + row * 64 + col];
    }
    __syncwarp();

    // lane l owns row h=l>>1 and the 8-column group gs=(l&1)*8 of the 16x16 score tile
    const int h = lane >> 1, gs = (lane & 1) * 8;
    float s[8];
#pragma unroll
    for (int gi = 0; gi < 8; gi++) s[gi] = 0.f;

#pragma unroll
    for (int dc = 0; dc < 4; dc++) {
        const float* qp = &sq[h * ROWP + dc * 16];
        float4 q0 = *(const float4*)(qp + 0);
        float4 q1 = *(const float4*)(qp + 4);
        float4 q2 = *(const float4*)(qp + 8);
        float4 q3 = *(const float4*)(qp + 12);
#pragma unroll
        for (int gi = 0; gi < 8; gi++) {
            const float* kp = &sk[(gs + gi) * ROWP + dc * 16];
            float4 k0 = *(const float4*)(kp + 0);
            float4 k1 = *(const float4*)(kp + 4);
            float4 k2 = *(const float4*)(kp + 8);
            float4 k3 = *(const float4*)(kp + 12);
            s[gi] += q0.x * k0.x + q0.y * k0.y + q0.z * k0.z + q0.w * k0.w
                   + q1.x * k1.x + q1.y * k1.y + q1.z * k1.z + q1.w * k1.w
                   + q2.x * k2.x + q2.y * k2.y + q2.z * k2.z + q2.w * k2.w
                   + q3.x * k3.x + q3.y * k3.y + q3.z * k3.z + q3.w * k3.w;
        }
    }

    // scale, mask, softmax across the 16-wide row (split over lane pairs)
    const float* mp = mg + (size_t)tok * 256 + h * 16 + gs;
    float mx = -1e30f;
#pragma unroll
    for (int gi = 0; gi < 8; gi++) {
        s[gi] = s[gi] * 0.125f - 1e9f * mp[gi];
        mx = fmaxf(mx, s[gi]);
    }
    mx = fmaxf(mx, __shfl_xor_sync(0xffffffffu, mx, 1));
    float sum = 0.f;
#pragma unroll
    for (int gi = 0; gi < 8; gi++) { s[gi] = expf(s[gi] - mx); sum += s[gi]; }
    sum += __shfl_xor_sync(0xffffffffu, sum, 1);
    const float inv = 1.0f / sum;
#pragma unroll
    for (int gi = 0; gi < 8; gi++) sw[h * 17 + gs + gi] = s[gi] * inv;
    __syncwarp();

    // out[h, dh..dh+31] = sum_g w[h,g] * v[g, dh..dh+31]
    const int dh = (lane & 1) * 32;
    float4 o[8];
#pragma unroll
    for (int j = 0; j < 8; j++) o[j] = make_float4(0.f, 0.f, 0.f, 0.f);
#pragma unroll
    for (int g = 0; g < 16; g++) {
        const float w = sw[h * 17 + g];
        const float* vp = &sv[g * ROWP + dh];
#pragma unroll
        for (int j = 0; j < 8; j++) {
            float4 vv = *(const float4*)&vp[j * 4];
            o[j].x += w * vv.x; o[j].y += w * vv.y;
            o[j].z += w * vv.z; o[j].w += w * vv.w;
        }
    }
    __syncwarp();   // everyone past q reads; safe to reuse sq as staging

    // stage output contiguously then write coalesced
#pragma unroll
    for (int j = 0; j < 8; j++) *(float4*)&sq[h * 64 + dh + j * 4] = o[j];
    __syncwarp();
    float* op = outg + base;
#pragma unroll
    for (int i = 0; i < 8; i++) {
        int idx = lane + i * 32;
        *(float4*)&op[idx * 4] = *(const float4*)&sq[idx * 4];
    }
}

// ---------------- launch ----------------
extern "C" void kernel_launch(void* const* d_in, const int* in_sizes, int n_in,
                              void* d_out, int out_size)
{
    const float* Q  = (const float*)d_in[0];
    const float* K  = (const float*)d_in[1];
    const float* V  = (const float*)d_in[2];
    const float* Msk= (const float*)d_in[3];
    const float* Wq = (const float*)d_in[4];
    const float* bq = (const float*)d_in[5];
    const float* Wk = (const float*)d_in[6];
    const float* bk = (const float*)d_in[7];
    const float* Wv = (const float*)d_in[8];
    const float* bv = (const float*)d_in[9];
    const float* Wo = (const float*)d_in[10];
    const float* bo = (const float*)d_in[11];
    float* out = (float*)d_out;

    float *gq, *gk, *gv, *ga;
    cudaGetSymbolAddress((void**)&gq, g_q);
    cudaGetSymbolAddress((void**)&gk, g_k);
    cudaGetSymbolAddress((void**)&gv, g_v);
    cudaGetSymbolAddress((void**)&ga, g_attn);

    cudaFuncSetAttribute(gemm_tf32, cudaFuncAttributeMaxDynamicSharedMemorySize, GEMM_SMEM);

    dim3 grid(NDIM / BN, MDIM / BM);   // (8, 128)
    gemm_tf32<<<grid, 256, GEMM_SMEM>>>(Q, Wq, bq, gq, nullptr);
    gemm_tf32<<<grid, 256, GEMM_SMEM>>>(K, Wk, bk, gk, nullptr);
    gemm_tf32<<<grid, 256, GEMM_SMEM>>>(V, Wv, bv, gv, nullptr);

    attn_kernel<<<MDIM / AT_WARPS, AT_WARPS * 32>>>(gq, gk, gv, Msk, ga);

    float* out2 = ((long long)out_size >= 2LL * MDIM * NDIM) ? out + (size_t)MDIM * NDIM
                                                             : nullptr;
    gemm_tf32<<<grid, 256, GEMM_SMEM>>>(ga, Wo, bo, out, out2);
}